// round 6
// baseline (speedup 1.0000x reference)
#include <cuda_runtime.h>

// 2-layer LSTM, B=2048 T=2048 H1=36 H2=1, fp32.
// R5: 2 warps/block, TWO seqs/block, grid 1024 -> 2048 resident warps
//     (13.8/SM, 2x R3/R4). Gate-split keeps W in 81 regs/warp:
//   warp0: gates i,f (+ L2 for t-1, + i/f of extra units 32..35)
//   warp1: gates g,o (+ all activations, h/hr writes, + g/o of extra units)

#define FULLMASK 0xffffffffu
#define H1C 36
#define TT 2048

__device__ __forceinline__ float2 ffma2(float2 a, float2 b, float2 c) {
    float2 d;
    asm("fma.rn.f32x2 %0, %1, %2, %3;"
        : "=l"(reinterpret_cast<unsigned long long&>(d))
        : "l"(reinterpret_cast<unsigned long long&>(a)),
          "l"(reinterpret_cast<unsigned long long&>(b)),
          "l"(reinterpret_cast<unsigned long long&>(c)));
    return d;
}
__device__ __forceinline__ float tanha(float x) {
    float y;
    asm("tanh.approx.f32 %0, %1;" : "=f"(y) : "f"(x));
    return y;
}
__device__ __forceinline__ float sigm(float x) {
    return fmaf(0.5f, tanha(0.5f * x), 0.5f);
}

struct Smem {
    float2 h[H1C];        // h per unit, 2 seqs
    float2 hr[H1C];       // relu(h)
    float2 gif[2][32];    // warp0 -> warp1: (i,f) preacts, per seq, per unit(lane)
    float2 eIF[8];        // extra units: i (0..3), f (4..7) preacts, 2 seqs
    float2 eGO[8];        // extra units: g (0..3), o (4..7) preacts, 2 seqs
};

__global__ void __launch_bounds__(64, 7)
lstm2_kernel(const float* __restrict__ x,
             const float* __restrict__ W_ih1, const float* __restrict__ W_hh1,
             const float* __restrict__ b_ih1, const float* __restrict__ b_hh1,
             const float* __restrict__ W_ih2, const float* __restrict__ W_hh2,
             const float* __restrict__ b_ih2, const float* __restrict__ b_hh2,
             float* __restrict__ out)
{
    __shared__ Smem sm;
    const int tid  = threadIdx.x;
    const int warp = tid >> 5;         // 0: i,f   1: g,o
    const int lane = tid & 31;
    const int seq0 = blockIdx.x * 2;

    // ---- register weights (direct LDG; W tiny, L2-resident) ----
    const int rA = warp * 72 + lane;        // i-row (w0) / g-row (w1), unit=lane
    const int rB = rA + H1C;                // f-row / o-row
    float2 Wp[H1C];
    #pragma unroll
    for (int j = 0; j < H1C; ++j)
        Wp[j] = make_float2(W_hh1[rA * H1C + j], W_hh1[rB * H1C + j]);
    const float2 wihP = make_float2(W_ih1[rA], W_ih1[rB]);
    const float2 bP   = make_float2(b_ih1[rA] + b_hh1[rA], b_ih1[rB] + b_hh1[rB]);

    // extra units 32..35: slot e = lane&7 (e<4: gateA, e>=4: gateB), j-range (lane>>3)*9..+9
    const int e   = lane & 7;
    const int grp = lane >> 3;
    const int jb  = grp * 9;
    const int rE  = warp * 72 + (e >> 2) * H1C + 32 + (e & 3);
    float WE[9];
    #pragma unroll
    for (int r = 0; r < 9; ++r)
        WE[r] = W_hh1[rE * H1C + jb + r];
    const float wihE = W_ih1[rE];
    const float bE   = b_ih1[rE] + b_hh1[rE];

    // L2 weights (used by warp0)
    const int q  = lane & 3;
    const int j0 = lane >> 2;
    float w2r[4];
    #pragma unroll
    for (int m = 0; m < 4; ++m)
        w2r[m] = W_ih2[q * H1C + j0 + 8 * m];
    const float w2x  = (j0 < 4) ? W_ih2[q * H1C + 32 + j0] : 0.0f;
    const float b2q  = b_ih2[q] + b_hh2[q];
    const float whq  = W_hh2[q];
    const float asc  = (q == 2) ? 1.0f : 0.5f;   // act = asc*tanh(asc*v)+aoc
    const float aoc  = (q == 2) ? 0.0f : 0.5f;

    if (tid < H1C) {
        sm.h[tid]  = make_float2(0.f, 0.f);
        sm.hr[tid] = make_float2(0.f, 0.f);
    }
    __syncthreads();

    const float* xb = x + (size_t)seq0 * TT;
    float* o0 = out + (size_t)seq0 * TT;
    float* o1 = o0 + TT;

    // states
    float c0 = 0.f, c1 = 0.f, cE = 0.f;                 // warp1
    float l2c0 = 0.f, l2c1 = 0.f, l2h0 = 0.f, l2h1 = 0.f; // warp0
    float ob0 = 0.f, ob1 = 0.f, xb0 = 0.f, xb1 = 0.f;

    // L2 pass for both seqs at step tp; reads sm.hr (step-tp values)
    auto l2pass = [&](int tp) {
        float sA = 0.f, sB = 0.f;
        #pragma unroll
        for (int m = 0; m < 4; ++m) {
            float2 hh = sm.hr[j0 + 8 * m];
            sA = fmaf(w2r[m], hh.x, sA);
            sB = fmaf(w2r[m], hh.y, sB);
        }
        if (j0 < 4) {
            float2 hh = sm.hr[32 + j0];
            sA = fmaf(w2x, hh.x, sA);
            sB = fmaf(w2x, hh.y, sB);
        }
        #pragma unroll
        for (int off = 4; off <= 16; off <<= 1) {
            sA += __shfl_xor_sync(FULLMASK, sA, off);
            sB += __shfl_xor_sync(FULLMASK, sB, off);
        }
        float vA = sA + b2q + whq * l2h0;
        float vB = sB + b2q + whq * l2h1;
        float aAct = fmaf(asc, tanha(asc * vA), aoc);  // sigm for q!=2, tanh for q==2
        float bAct = fmaf(asc, tanha(asc * vB), aoc);
        const int base = lane & ~3;
        float iA = __shfl_sync(FULLMASK, aAct, base + 0);
        float fA = __shfl_sync(FULLMASK, aAct, base + 1);
        float gA = __shfl_sync(FULLMASK, aAct, base + 2);
        float oA = __shfl_sync(FULLMASK, aAct, base + 3);
        float iB = __shfl_sync(FULLMASK, bAct, base + 0);
        float fB = __shfl_sync(FULLMASK, bAct, base + 1);
        float gB = __shfl_sync(FULLMASK, bAct, base + 2);
        float oB = __shfl_sync(FULLMASK, bAct, base + 3);
        l2c0 = fmaf(fA, l2c0, iA * gA);
        l2h0 = oA * tanha(l2c0);
        l2c1 = fmaf(fB, l2c1, iB * gB);
        l2h1 = oB * tanha(l2c1);
        const int tmp = tp & 31;
        ob0 = (tmp == lane) ? l2h0 : ob0;
        ob1 = (tmp == lane) ? l2h1 : ob1;
        if (tmp == 31) {
            o0[tp - 31 + lane] = ob0;
            o1[tp - 31 + lane] = ob1;
        }
    };

    for (int t = 0; t < TT; ++t) {
        const int tm = t & 31;
        if (tm == 0) {
            xb0 = xb[t + lane];
            xb1 = xb[TT + t + lane];
        }
        const float x0 = __shfl_sync(FULLMASK, xb0, tm);
        const float x1 = __shfl_sync(FULLMASK, xb1, tm);

        // ---- main j-loop: split-half acc chains (4 independent), 2 seqs
        float2 a0 = ffma2(make_float2(x0, x0), wihP, bP);
        float2 a1 = ffma2(make_float2(x1, x1), wihP, bP);
        float2 d0 = make_float2(0.f, 0.f), d1 = d0;
        #pragma unroll
        for (int j = 0; j < 18; ++j) {
            float2 h2 = sm.h[j];
            a0 = ffma2(Wp[j], make_float2(h2.x, h2.x), a0);
            a1 = ffma2(Wp[j], make_float2(h2.y, h2.y), a1);
        }
        #pragma unroll
        for (int j = 18; j < H1C; ++j) {
            float2 h2 = sm.h[j];
            d0 = ffma2(Wp[j], make_float2(h2.x, h2.x), d0);
            d1 = ffma2(Wp[j], make_float2(h2.y, h2.y), d1);
        }
        a0.x += d0.x; a0.y += d0.y;
        a1.x += d1.x; a1.y += d1.y;

        // ---- extra units partials (4-lane split per slot) + reduce
        float aE0 = (grp == 0) ? fmaf(x0, wihE, bE) : 0.f;
        float aE1 = (grp == 0) ? fmaf(x1, wihE, bE) : 0.f;
        #pragma unroll
        for (int r = 0; r < 9; ++r) {
            float2 h2 = sm.h[jb + r];
            aE0 = fmaf(WE[r], h2.x, aE0);
            aE1 = fmaf(WE[r], h2.y, aE1);
        }
        aE0 += __shfl_xor_sync(FULLMASK, aE0, 8);
        aE1 += __shfl_xor_sync(FULLMASK, aE1, 8);
        aE0 += __shfl_xor_sync(FULLMASK, aE0, 16);
        aE1 += __shfl_xor_sync(FULLMASK, aE1, 16);

        if (warp == 0) {
            // L2 for previous step (reads hr(t-1): still valid pre-barrier)
            if (t) l2pass(t - 1);
            // hand off i,f preacts
            sm.gif[0][lane] = a0;
            sm.gif[1][lane] = a1;
            if (lane < 8) sm.eIF[lane] = make_float2(aE0, aE1);
        } else {
            if (lane < 8) sm.eGO[lane] = make_float2(aE0, aE1);
        }
        __syncthreads();   // bar1: preacts visible; hr(t-1) reads complete

        if (warp == 1) {
            // main activations: unit = lane; i,f from smem; g,o = own regs
            float2 if0 = sm.gif[0][lane];
            float2 if1 = sm.gif[1][lane];
            float h0v, h1v;
            {
                float iv = sigm(if0.x), fv = sigm(if0.y), gv = tanha(a0.x), ov = sigm(a0.y);
                c0 = fmaf(fv, c0, iv * gv);  h0v = ov * tanha(c0);
            }
            {
                float iv = sigm(if1.x), fv = sigm(if1.y), gv = tanha(a1.x), ov = sigm(a1.y);
                c1 = fmaf(fv, c1, iv * gv);  h1v = ov * tanha(c1);
            }
            sm.h[lane]  = make_float2(h0v, h1v);
            sm.hr[lane] = make_float2(fmaxf(h0v, 0.f), fmaxf(h1v, 0.f));
            // extra units: lane = s*4 + u (lane < 8): s = seq, u = unit
            if (lane < 8) {
                const int s = lane >> 2, u = lane & 3;
                const float iv = sigm(((const float*)&sm.eIF[u])[s]);
                const float fv = sigm(((const float*)&sm.eIF[4 + u])[s]);
                const float gv = tanha(((const float*)&sm.eGO[u])[s]);
                const float ov = sigm(((const float*)&sm.eGO[4 + u])[s]);
                cE = fmaf(fv, cE, iv * gv);
                float hv = ov * tanha(cE);
                ((float*)&sm.h[32 + u])[s]  = hv;
                ((float*)&sm.hr[32 + u])[s] = fmaxf(hv, 0.f);
            }
        }
        __syncthreads();   // bar2: h(t)/hr(t) visible to both warps
    }

    if (warp == 0) l2pass(TT - 1);   // final step's L2 + output flush
}

extern "C" void kernel_launch(void* const* d_in, const int* in_sizes, int n_in,
                              void* d_out, int out_size)
{
    const float* x     = (const float*)d_in[0];
    const float* W_ih1 = (const float*)d_in[1];
    const float* W_hh1 = (const float*)d_in[2];
    const float* b_ih1 = (const float*)d_in[3];
    const float* b_hh1 = (const float*)d_in[4];
    const float* W_ih2 = (const float*)d_in[5];
    const float* W_hh2 = (const float*)d_in[6];
    const float* b_ih2 = (const float*)d_in[7];
    const float* b_hh2 = (const float*)d_in[8];

    const int B = in_sizes[0] / TT;   // x is [B, T, 1]
    lstm2_kernel<<<B / 2, 64>>>(x, W_ih1, W_hh1, b_ih1, b_hh1,
                                W_ih2, W_hh2, b_ih2, b_hh2,
                                (float*)d_out);
}

// round 7
// speedup vs baseline: 1.3680x; 1.3680x over previous
#include <cuda_runtime.h>

// 2-layer LSTM, B=2048 T=2048 H1=36 H2=1, fp32.
// R6: R3 base (1 warp / 2 seqs, full W in regs, unit-major slots) with:
//   - outer(64) x inner(32) loop: no per-step branches (x LDG + out flush hoisted)
//   - pre-duplicated h smem (hdA/hdB) -> 8 instr per j
//   - 1-MUFU pre-gather activations for extra units and L2
//   - x double-buffer prefetch
//   - L2 at end of step t (reads hr(t)), two __syncwarp/step for smem ordering

#define FULLMASK 0xffffffffu
#define H1C 36
#define TT 2048

__device__ __forceinline__ float2 ffma2(float2 a, float2 b, float2 c) {
    float2 d;
    asm("fma.rn.f32x2 %0, %1, %2, %3;"
        : "=l"(reinterpret_cast<unsigned long long&>(d))
        : "l"(reinterpret_cast<unsigned long long&>(a)),
          "l"(reinterpret_cast<unsigned long long&>(b)),
          "l"(reinterpret_cast<unsigned long long&>(c)));
    return d;
}
__device__ __forceinline__ float tanha(float x) {
    float y;
    asm("tanh.approx.f32 %0, %1;" : "=f"(y) : "f"(x));
    return y;
}
__device__ __forceinline__ float sigm(float x) {
    return fmaf(0.5f, tanha(0.5f * x), 0.5f);
}

struct Smem {
    float2 hdA[H1C];   // (hA, hA) per unit
    float2 hdB[H1C];   // (hB, hB)
    float2 h[H1C];     // (hA, hB)
    float2 hr[40];     // relu(h), padded: [36..39] stay 0
};

__global__ void __launch_bounds__(32)
lstm2_kernel(const float* __restrict__ x,
             const float* __restrict__ W_ih1, const float* __restrict__ W_hh1,
             const float* __restrict__ b_ih1, const float* __restrict__ b_hh1,
             const float* __restrict__ W_ih2, const float* __restrict__ W_hh2,
             const float* __restrict__ b_ih2, const float* __restrict__ b_hh2,
             float* __restrict__ out)
{
    __shared__ Smem sm;
    const int lane = threadIdx.x;
    const int seqA = blockIdx.x * 2;

    // lane's slots: (i,f,g,o) of unit=lane; 5th slot (lane<16):
    // gate (lane>>2) of unit 32+(lane&3)
    const int r0 = lane, r1 = H1C + lane, r2 = 2 * H1C + lane, r3 = 3 * H1C + lane;
    const bool eok = lane < 16;
    const int r4 = eok ? ((lane >> 2) * H1C + 32 + (lane & 3)) : 0;

    float2 Wp01[H1C], Wp23[H1C];
    float  W4[H1C];
    #pragma unroll
    for (int j = 0; j < H1C; ++j) {
        Wp01[j] = make_float2(W_hh1[r0 * H1C + j], W_hh1[r1 * H1C + j]);
        Wp23[j] = make_float2(W_hh1[r2 * H1C + j], W_hh1[r3 * H1C + j]);
        W4[j]   = eok ? W_hh1[r4 * H1C + j] : 0.0f;
    }
    const float2 wih01 = make_float2(W_ih1[r0], W_ih1[r1]);
    const float2 wih23 = make_float2(W_ih1[r2], W_ih1[r3]);
    const float  wih4  = eok ? W_ih1[r4] : 0.0f;
    const float2 bs01  = make_float2(b_ih1[r0] + b_hh1[r0], b_ih1[r1] + b_hh1[r1]);
    const float2 bs23  = make_float2(b_ih1[r2] + b_hh1[r2], b_ih1[r3] + b_hh1[r3]);
    const float  bs4   = eok ? (b_ih1[r4] + b_hh1[r4]) : 0.0f;

    const float esc = ((lane >> 2) == 2) ? 1.0f : 0.5f;  // extra-unit pre-act
    const float eof = ((lane >> 2) == 2) ? 0.0f : 0.5f;
    const int   u   = lane & 3;

    const int q  = lane & 3;
    const int j0 = lane >> 2;
    float w2r[4];
    #pragma unroll
    for (int m = 0; m < 4; ++m)
        w2r[m] = W_ih2[q * H1C + j0 + 8 * m];
    const float w2x = (j0 < 4) ? W_ih2[q * H1C + 32 + j0] : 0.0f;
    const float b2q = b_ih2[q] + b_hh2[q];
    const float whq = W_hh2[q];
    const float asc = (q == 2) ? 1.0f : 0.5f;
    const float aoc = (q == 2) ? 0.0f : 0.5f;

    if (lane < H1C) {
        sm.hdA[lane] = make_float2(0.f, 0.f);
        sm.hdB[lane] = make_float2(0.f, 0.f);
        sm.h[lane]   = make_float2(0.f, 0.f);
    }
    sm.hr[lane] = make_float2(0.f, 0.f);
    if (lane < 8) sm.hr[32 + lane] = make_float2(0.f, 0.f);
    __syncthreads();

    const float* xA = x   + (size_t)seqA * TT;
    const float* xB = xA + TT;
    float*       oA = out + (size_t)seqA * TT;
    float*       oB = oA + TT;

    float cA = 0.f, cB = 0.f, cEA = 0.f, cEB = 0.f;
    float l2cA = 0.f, l2cB = 0.f, l2hA = 0.f, l2hB = 0.f;
    float obA = 0.f, obB = 0.f;

    float xcA = xA[lane];
    float xcB = xB[lane];

    for (int tb = 0; tb < TT / 32; ++tb) {
        const int nb = (tb < TT / 32 - 1) ? tb + 1 : tb;
        const float xnA = xA[nb * 32 + lane];
        const float xnB = xB[nb * 32 + lane];

        #pragma unroll 1
        for (int tm = 0; tm < 32; ++tm) {
            const float xa = __shfl_sync(FULLMASK, xcA, tm);
            const float xb = __shfl_sync(FULLMASK, xcB, tm);

            // ---- L1 gate accumulation
            float2 aA01 = ffma2(make_float2(xa, xa), wih01, bs01);
            float2 aA23 = ffma2(make_float2(xa, xa), wih23, bs23);
            float2 aB01 = ffma2(make_float2(xb, xb), wih01, bs01);
            float2 aB23 = ffma2(make_float2(xb, xb), wih23, bs23);
            float  aA4  = fmaf(xa, wih4, bs4);
            float  aB4  = fmaf(xb, wih4, bs4);
            #pragma unroll
            for (int j = 0; j < H1C; ++j) {
                const float2 hA2 = sm.hdA[j];
                const float2 hB2 = sm.hdB[j];
                aA01 = ffma2(Wp01[j], hA2, aA01);
                aA23 = ffma2(Wp23[j], hA2, aA23);
                aB01 = ffma2(Wp01[j], hB2, aB01);
                aB23 = ffma2(Wp23[j], hB2, aB23);
                aA4  = fmaf(W4[j], hA2.x, aA4);
                aB4  = fmaf(W4[j], hB2.x, aB4);
            }

            // ---- main activations (unit = lane)
            {
                const float iA = sigm(aA01.x), fA = sigm(aA01.y);
                const float gA = tanha(aA23.x), oAa = sigm(aA23.y);
                cA = fmaf(fA, cA, iA * gA);
                const float hA = oAa * tanha(cA);
                const float iB = sigm(aB01.x), fB = sigm(aB01.y);
                const float gB = tanha(aB23.x), oBa = sigm(aB23.y);
                cB = fmaf(fB, cB, iB * gB);
                const float hB = oBa * tanha(cB);
                sm.hdA[lane] = make_float2(hA, hA);
                sm.hdB[lane] = make_float2(hB, hB);
                sm.h[lane]   = make_float2(hA, hB);
                sm.hr[lane]  = make_float2(fmaxf(hA, 0.f), fmaxf(hB, 0.f));
            }
            // ---- extra units 32..35: pre-gather 1-MUFU act, branch-free
            {
                const float eAv = fmaf(esc, tanha(esc * aA4), eof);
                const float eBv = fmaf(esc, tanha(esc * aB4), eof);
                const float iA = __shfl_sync(FULLMASK, eAv, u);
                const float fA = __shfl_sync(FULLMASK, eAv, u + 4);
                const float gA = __shfl_sync(FULLMASK, eAv, u + 8);
                const float oAe = __shfl_sync(FULLMASK, eAv, u + 12);
                const float iB = __shfl_sync(FULLMASK, eBv, u);
                const float fB = __shfl_sync(FULLMASK, eBv, u + 4);
                const float gB = __shfl_sync(FULLMASK, eBv, u + 8);
                const float oBe = __shfl_sync(FULLMASK, eBv, u + 12);
                cEA = fmaf(fA, cEA, iA * gA);      // every lane computes unit 32+u
                cEB = fmaf(fB, cEB, iB * gB);
                const float hEA = oAe * tanha(cEA);
                const float hEB = oBe * tanha(cEB);
                if (lane < 4) {                    // tiny store-only block
                    sm.hdA[32 + u] = make_float2(hEA, hEA);
                    sm.hdB[32 + u] = make_float2(hEB, hEB);
                    sm.h[32 + u]   = make_float2(hEA, hEB);
                    sm.hr[32 + u]  = make_float2(fmaxf(hEA, 0.f), fmaxf(hEB, 0.f));
                }
            }
            __syncwarp();   // act stores visible before L2 reads hr

            // ---- L2 for step t
            {
                float sA = 0.f, sB = 0.f;
                #pragma unroll
                for (int m = 0; m < 4; ++m) {
                    const float2 hh = sm.hr[j0 + 8 * m];
                    sA = fmaf(w2r[m], hh.x, sA);
                    sB = fmaf(w2r[m], hh.y, sB);
                }
                const float2 hx = sm.hr[32 + j0];
                sA = fmaf(w2x, hx.x, sA);
                sB = fmaf(w2x, hx.y, sB);
                #pragma unroll
                for (int off = 4; off <= 16; off <<= 1) {
                    sA += __shfl_xor_sync(FULLMASK, sA, off);
                    sB += __shfl_xor_sync(FULLMASK, sB, off);
                }
                const float vA = fmaf(whq, l2hA, sA + b2q);
                const float vB = fmaf(whq, l2hB, sB + b2q);
                const float aAct = fmaf(asc, tanha(asc * vA), aoc);
                const float bAct = fmaf(asc, tanha(asc * vB), aoc);
                const int base = lane & ~3;
                const float iA = __shfl_sync(FULLMASK, aAct, base + 0);
                const float fA = __shfl_sync(FULLMASK, aAct, base + 1);
                const float gA = __shfl_sync(FULLMASK, aAct, base + 2);
                const float oA2 = __shfl_sync(FULLMASK, aAct, base + 3);
                const float iB = __shfl_sync(FULLMASK, bAct, base + 0);
                const float fB = __shfl_sync(FULLMASK, bAct, base + 1);
                const float gB = __shfl_sync(FULLMASK, bAct, base + 2);
                const float oB2 = __shfl_sync(FULLMASK, bAct, base + 3);
                l2cA = fmaf(fA, l2cA, iA * gA);
                l2hA = oA2 * tanha(l2cA);
                l2cB = fmaf(fB, l2cB, iB * gB);
                l2hB = oB2 * tanha(l2cB);
                obA = (tm == lane) ? l2hA : obA;
                obB = (tm == lane) ? l2hB : obB;
            }
            __syncwarp();   // L2 hr reads complete before next step's act stores
        }

        oA[tb * 32 + lane] = obA;
        oB[tb * 32 + lane] = obB;
        xcA = xnA;
        xcB = xnB;
    }
}

extern "C" void kernel_launch(void* const* d_in, const int* in_sizes, int n_in,
                              void* d_out, int out_size)
{
    const float* x     = (const float*)d_in[0];
    const float* W_ih1 = (const float*)d_in[1];
    const float* W_hh1 = (const float*)d_in[2];
    const float* b_ih1 = (const float*)d_in[3];
    const float* b_hh1 = (const float*)d_in[4];
    const float* W_ih2 = (const float*)d_in[5];
    const float* W_hh2 = (const float*)d_in[6];
    const float* b_ih2 = (const float*)d_in[7];
    const float* b_hh2 = (const float*)d_in[8];

    const int B = in_sizes[0] / TT;   // x is [B, T, 1]
    lstm2_kernel<<<B / 2, 32>>>(x, W_ih1, W_hh1, b_ih1, b_hh1,
                                W_ih2, W_hh2, b_ih2, b_hh2,
                                (float*)d_out);
}

// round 8
// speedup vs baseline: 1.4722x; 1.0762x over previous
#include <cuda_runtime.h>

// 2-layer LSTM, B=2048 T=2048 H1=36 H2=1, fp32.
// R7: 1 warp / 2 seqs (1024 blocks). Full W in regs, unit-major slots.
//   - lag-1 L2 pipeline: body = { jloop(t); L2(t-1); acts(t) }, step 0 peeled
//   - flattened 64x(31+1) loop, zero per-step branches, flush after each chunk
//   - hd4 = (hA,hA,hB,hB) float4 smem -> 1 LDS.128 per j
//   - no __syncwarp: convergent warp, program-ordered same-warp STS->LDS

#define FULLMASK 0xffffffffu
#define H1C 36
#define TT 2048

__device__ __forceinline__ float2 ffma2(float2 a, float2 b, float2 c) {
    float2 d;
    asm("fma.rn.f32x2 %0, %1, %2, %3;"
        : "=l"(reinterpret_cast<unsigned long long&>(d))
        : "l"(reinterpret_cast<unsigned long long&>(a)),
          "l"(reinterpret_cast<unsigned long long&>(b)),
          "l"(reinterpret_cast<unsigned long long&>(c)));
    return d;
}
__device__ __forceinline__ float tanha(float x) {
    float y;
    asm("tanh.approx.f32 %0, %1;" : "=f"(y) : "f"(x));
    return y;
}
__device__ __forceinline__ float sigm(float x) {
    return fmaf(0.5f, tanha(0.5f * x), 0.5f);
}

struct Smem {
    float4 hd4[40];   // (hA, hA, hB, hB) per unit; [36..39] pad = 0
    float2 hr[40];    // (relu(hA), relu(hB)); [36..39] pad = 0
};

__global__ void __launch_bounds__(32)
lstm2_kernel(const float* __restrict__ x,
             const float* __restrict__ W_ih1, const float* __restrict__ W_hh1,
             const float* __restrict__ b_ih1, const float* __restrict__ b_hh1,
             const float* __restrict__ W_ih2, const float* __restrict__ W_hh2,
             const float* __restrict__ b_ih2, const float* __restrict__ b_hh2,
             float* __restrict__ out)
{
    __shared__ Smem sm;
    const int lane = threadIdx.x;
    const int seqA = blockIdx.x * 2;

    // lane's slots: (i,f,g,o) of unit=lane; 5th slot (lane<16):
    // gate (lane>>2) of unit 32+(lane&3)
    const int r0 = lane, r1 = H1C + lane, r2 = 2 * H1C + lane, r3 = 3 * H1C + lane;
    const bool eok = lane < 16;
    const int r4 = eok ? ((lane >> 2) * H1C + 32 + (lane & 3)) : 0;

    float2 Wp01[H1C], Wp23[H1C];
    float  W4[H1C];
    #pragma unroll
    for (int j = 0; j < H1C; ++j) {
        Wp01[j] = make_float2(W_hh1[r0 * H1C + j], W_hh1[r1 * H1C + j]);
        Wp23[j] = make_float2(W_hh1[r2 * H1C + j], W_hh1[r3 * H1C + j]);
        W4[j]   = eok ? W_hh1[r4 * H1C + j] : 0.0f;
    }
    const float2 wih01 = make_float2(W_ih1[r0], W_ih1[r1]);
    const float2 wih23 = make_float2(W_ih1[r2], W_ih1[r3]);
    const float  wih4  = eok ? W_ih1[r4] : 0.0f;
    const float2 bs01  = make_float2(b_ih1[r0] + b_hh1[r0], b_ih1[r1] + b_hh1[r1]);
    const float2 bs23  = make_float2(b_ih1[r2] + b_hh1[r2], b_ih1[r3] + b_hh1[r3]);
    const float  bs4   = eok ? (b_ih1[r4] + b_hh1[r4]) : 0.0f;

    const float esc = ((lane >> 2) == 2) ? 1.0f : 0.5f;  // extra-unit pre-act
    const float eof = ((lane >> 2) == 2) ? 0.0f : 0.5f;
    const int   u   = lane & 3;

    const int q  = lane & 3;
    const int j0 = lane >> 2;
    float w2r[4];
    #pragma unroll
    for (int m = 0; m < 4; ++m)
        w2r[m] = W_ih2[q * H1C + j0 + 8 * m];
    const float w2x = (j0 < 4) ? W_ih2[q * H1C + 32 + j0] : 0.0f;
    const float b2q = b_ih2[q] + b_hh2[q];
    const float whq = W_hh2[q];
    const float asc = (q == 2) ? 1.0f : 0.5f;
    const float aoc = (q == 2) ? 0.0f : 0.5f;

    if (lane < 20) {
        sm.hd4[2 * lane]     = make_float4(0.f, 0.f, 0.f, 0.f);
        sm.hd4[2 * lane + 1] = make_float4(0.f, 0.f, 0.f, 0.f);
    }
    sm.hr[lane] = make_float2(0.f, 0.f);
    if (lane < 8) sm.hr[32 + lane] = make_float2(0.f, 0.f);
    __syncthreads();

    const float* xA = x   + (size_t)seqA * TT;
    const float* xB = xA + TT;
    float*       oA = out + (size_t)seqA * TT;
    float*       oB = oA + TT;

    float cA = 0.f, cB = 0.f, cEA = 0.f, cEB = 0.f;
    float l2cA = 0.f, l2cB = 0.f, l2hA = 0.f, l2hB = 0.f;
    float obA = 0.f, obB = 0.f;

    // gate accumulators (shared across lambdas)
    float2 aA01, aA23, aB01, aB23;
    float  aA4, aB4;

    // ---- L1 gate accumulation for step t (reads hd4(t-1))
    auto jloop = [&](float xa, float xb) {
        aA01 = ffma2(make_float2(xa, xa), wih01, bs01);
        aA23 = ffma2(make_float2(xa, xa), wih23, bs23);
        aB01 = ffma2(make_float2(xb, xb), wih01, bs01);
        aB23 = ffma2(make_float2(xb, xb), wih23, bs23);
        aA4  = fmaf(xa, wih4, bs4);
        aB4  = fmaf(xb, wih4, bs4);
        #pragma unroll
        for (int j = 0; j < H1C; ++j) {
            const float4 h4 = sm.hd4[j];
            const float2 hA2 = make_float2(h4.x, h4.y);
            const float2 hB2 = make_float2(h4.z, h4.w);
            aA01 = ffma2(Wp01[j], hA2, aA01);
            aA23 = ffma2(Wp23[j], hA2, aA23);
            aB01 = ffma2(Wp01[j], hB2, aB01);
            aB23 = ffma2(Wp23[j], hB2, aB23);
            aA4  = fmaf(W4[j], h4.x, aA4);
            aB4  = fmaf(W4[j], h4.z, aB4);
        }
    };

    // ---- L2 for the PREVIOUS step (reads hr(t-1)); tpmod = (t-1)&31
    auto l2step = [&](int tpmod) {
        float sA = 0.f, sB = 0.f;
        #pragma unroll
        for (int m = 0; m < 4; ++m) {
            const float2 hh = sm.hr[j0 + 8 * m];
            sA = fmaf(w2r[m], hh.x, sA);
            sB = fmaf(w2r[m], hh.y, sB);
        }
        const float2 hx = sm.hr[32 + j0];
        sA = fmaf(w2x, hx.x, sA);
        sB = fmaf(w2x, hx.y, sB);
        #pragma unroll
        for (int off = 4; off <= 16; off <<= 1) {
            sA += __shfl_xor_sync(FULLMASK, sA, off);
            sB += __shfl_xor_sync(FULLMASK, sB, off);
        }
        const float vA = fmaf(whq, l2hA, sA + b2q);
        const float vB = fmaf(whq, l2hB, sB + b2q);
        const float aAct = fmaf(asc, tanha(asc * vA), aoc);
        const float bAct = fmaf(asc, tanha(asc * vB), aoc);
        const int base = lane & ~3;
        const float iA = __shfl_sync(FULLMASK, aAct, base + 0);
        const float fA = __shfl_sync(FULLMASK, aAct, base + 1);
        const float gA = __shfl_sync(FULLMASK, aAct, base + 2);
        const float oA2 = __shfl_sync(FULLMASK, aAct, base + 3);
        const float iB = __shfl_sync(FULLMASK, bAct, base + 0);
        const float fB = __shfl_sync(FULLMASK, bAct, base + 1);
        const float gB = __shfl_sync(FULLMASK, bAct, base + 2);
        const float oB2 = __shfl_sync(FULLMASK, bAct, base + 3);
        l2cA = fmaf(fA, l2cA, iA * gA);
        l2hA = oA2 * tanha(l2cA);
        l2cB = fmaf(fB, l2cB, iB * gB);
        l2hB = oB2 * tanha(l2cB);
        obA = (tpmod == lane) ? l2hA : obA;
        obB = (tpmod == lane) ? l2hB : obB;
    };

    // ---- activations for step t (writes hd4(t), hr(t))
    auto acts = [&]() {
        {
            const float iA = sigm(aA01.x), fA = sigm(aA01.y);
            const float gA = tanha(aA23.x), oAa = sigm(aA23.y);
            cA = fmaf(fA, cA, iA * gA);
            const float hA = oAa * tanha(cA);
            const float iB = sigm(aB01.x), fB = sigm(aB01.y);
            const float gB = tanha(aB23.x), oBa = sigm(aB23.y);
            cB = fmaf(fB, cB, iB * gB);
            const float hB = oBa * tanha(cB);
            sm.hd4[lane] = make_float4(hA, hA, hB, hB);
            sm.hr[lane]  = make_float2(fmaxf(hA, 0.f), fmaxf(hB, 0.f));
        }
        {   // extra units 32..35 (pre-gather 1-MUFU act, branch-free compute)
            const float eAv = fmaf(esc, tanha(esc * aA4), eof);
            const float eBv = fmaf(esc, tanha(esc * aB4), eof);
            const float iA = __shfl_sync(FULLMASK, eAv, u);
            const float fA = __shfl_sync(FULLMASK, eAv, u + 4);
            const float gA = __shfl_sync(FULLMASK, eAv, u + 8);
            const float oAe = __shfl_sync(FULLMASK, eAv, u + 12);
            const float iB = __shfl_sync(FULLMASK, eBv, u);
            const float fB = __shfl_sync(FULLMASK, eBv, u + 4);
            const float gB = __shfl_sync(FULLMASK, eBv, u + 8);
            const float oBe = __shfl_sync(FULLMASK, eBv, u + 12);
            cEA = fmaf(fA, cEA, iA * gA);
            cEB = fmaf(fB, cEB, iB * gB);
            const float hEA = oAe * tanha(cEA);
            const float hEB = oBe * tanha(cEB);
            if (lane < 4) {
                sm.hd4[32 + u] = make_float4(hEA, hEA, hEB, hEB);
                sm.hr[32 + u]  = make_float2(fmaxf(hEA, 0.f), fmaxf(hEB, 0.f));
            }
        }
    };

    float xcA = xA[lane];          // x chunk 0
    float xcB = xB[lane];

    // ---- peel step 0 (h = 0: gate preacts are bias-only)
    {
        const float xa = __shfl_sync(FULLMASK, xcA, 0);
        const float xb = __shfl_sync(FULLMASK, xcB, 0);
        aA01 = ffma2(make_float2(xa, xa), wih01, bs01);
        aA23 = ffma2(make_float2(xa, xa), wih23, bs23);
        aB01 = ffma2(make_float2(xb, xb), wih01, bs01);
        aB23 = ffma2(make_float2(xb, xb), wih23, bs23);
        aA4  = fmaf(xa, wih4, bs4);
        aB4  = fmaf(xb, wih4, bs4);
        acts();
    }

    // ---- main: blocks 0..62 (inner s=1..31, then s=32 body, then flush)
    for (int tb = 0; tb < 63; ++tb) {
        const float xnA = xA[(tb + 1) * 32 + lane];   // next chunk prefetch
        const float xnB = xB[(tb + 1) * 32 + lane];

        #pragma unroll 1
        for (int s = 1; s < 32; ++s) {
            const float xa = __shfl_sync(FULLMASK, xcA, s);
            const float xb = __shfl_sync(FULLMASK, xcB, s);
            jloop(xa, xb);
            l2step(s - 1);       // L2 of step t-1
            acts();
        }
        {   // s = 32: first step of the next chunk; its L2 closes this chunk
            const float xa = __shfl_sync(FULLMASK, xnA, 0);
            const float xb = __shfl_sync(FULLMASK, xnB, 0);
            jloop(xa, xb);
            l2step(31);
            acts();
        }
        oA[tb * 32 + lane] = obA;       // flush chunk tb (steps tb*32 .. +31)
        oB[tb * 32 + lane] = obB;
        xcA = xnA;
        xcB = xnB;
    }

    // ---- last block (tb = 63): steps 2017..2047, then final L2 + flush
    #pragma unroll 1
    for (int s = 1; s < 32; ++s) {
        const float xa = __shfl_sync(FULLMASK, xcA, s);
        const float xb = __shfl_sync(FULLMASK, xcB, s);
        jloop(xa, xb);
        l2step(s - 1);
        acts();
    }
    l2step(31);                         // L2 of step 2047
    oA[63 * 32 + lane] = obA;
    oB[63 * 32 + lane] = obB;
}

extern "C" void kernel_launch(void* const* d_in, const int* in_sizes, int n_in,
                              void* d_out, int out_size)
{
    const float* x     = (const float*)d_in[0];
    const float* W_ih1 = (const float*)d_in[1];
    const float* W_hh1 = (const float*)d_in[2];
    const float* b_ih1 = (const float*)d_in[3];
    const float* b_hh1 = (const float*)d_in[4];
    const float* W_ih2 = (const float*)d_in[5];
    const float* W_hh2 = (const float*)d_in[6];
    const float* b_ih2 = (const float*)d_in[7];
    const float* b_hh2 = (const float*)d_in[8];

    const int B = in_sizes[0] / TT;   // x is [B, T, 1]
    lstm2_kernel<<<B / 2, 32>>>(x, W_ih1, W_hh1, b_ih1, b_hh1,
                                W_ih2, W_hh2, b_ih2, b_hh2,
                                (float*)d_out);
}